// round 15
// baseline (speedup 1.0000x reference)
#include <cuda_runtime.h>
#include <cuda_bf16.h>
#include <cuda_fp8.h>
#include <cstdint>

#define BATCH 4096
#define DIM   256
#define NNEG  32768

// ---------------- scratch (device globals; no allocs allowed) ----------------
__device__ float g_rowsum[BATCH];
__device__ float g_colsum[BATCH];
__device__ float g_negsum[BATCH];
__device__ float g_diagdot[BATCH];      // exact fp32 q_i . p_i
__device__ int   g_off[BATCH];          // exclusive prefix of counts
__device__ uint32_t g_q8[BATCH * DIM / 4];   // e4m3x4 packed
__device__ uint32_t g_p8[BATCH * DIM / 4];

__device__ __forceinline__ uint32_t smem_u32(const void* p) {
    uint32_t a;
    asm("{ .reg .u64 t; cvta.to.shared.u64 t, %1; cvt.u32.u64 %0, t; }" : "=r"(a) : "l"(p));
    return a;
}

__device__ __forceinline__ float inv_tau(const float* log_tau) {
    float t = expf(log_tau[0]);
    t = fminf(fmaxf(t, 1e-4f), 1.0f);
    return 1.0f / t;
}

__device__ __forceinline__ float ex2(float x) {
    float r;
    asm("ex2.approx.f32 %0, %1;" : "=f"(r) : "f"(x));
    return r;
}
#define LOG2E 1.4426950408889634f

// ---------------- convert + scan, one launch ----------------
// Blocks 0..511: 256 threads, 2 float4 each of q and p; warp w == one row -> exact diag.
// Block 512: zero accumulators + exclusive scan of counts (16 per thread).
__global__ void convert_scan_kernel(const float* __restrict__ q, const float* __restrict__ p,
                                    const int* __restrict__ counts) {
    int tid = threadIdx.x;
    if (blockIdx.x < 512) {
        int idx0 = blockIdx.x * 512 + tid * 2;
        const float4 qa0 = ((const float4*)q)[idx0];
        const float4 qa1 = ((const float4*)q)[idx0 + 1];
        const float4 pa0 = ((const float4*)p)[idx0];
        const float4 pa1 = ((const float4*)p)[idx0 + 1];
        __nv_fp8x4_e4m3 q80(qa0), q81(qa1), p80(pa0), p81(pa1);
        g_q8[idx0]     = *reinterpret_cast<uint32_t*>(&q80);
        g_q8[idx0 + 1] = *reinterpret_cast<uint32_t*>(&q81);
        g_p8[idx0]     = *reinterpret_cast<uint32_t*>(&p80);
        g_p8[idx0 + 1] = *reinterpret_cast<uint32_t*>(&p81);
        // exact diag: warp w covers row blockIdx.x*8 + w entirely
        float part = qa0.x * pa0.x + qa0.y * pa0.y + qa0.z * pa0.z + qa0.w * pa0.w
                   + qa1.x * pa1.x + qa1.y * pa1.y + qa1.z * pa1.z + qa1.w * pa1.w;
        #pragma unroll
        for (int m = 16; m >= 1; m >>= 1)
            part += __shfl_xor_sync(0xffffffffu, part, m);
        if ((tid & 31) == 0)
            g_diagdot[blockIdx.x * 8 + (tid >> 5)] = part;
        return;
    }
    // ---- block 512: zero + scan ----
    float4 z4 = make_float4(0.f, 0.f, 0.f, 0.f);
    #pragma unroll
    for (int j = 0; j < 4; j++) {
        ((float4*)g_rowsum)[tid * 4 + j] = z4;
        ((float4*)g_colsum)[tid * 4 + j] = z4;
        ((float4*)g_negsum)[tid * 4 + j] = z4;
    }
    __shared__ int wsum[8];
    int lane = tid & 31, w = tid >> 5;
    int4 c[4];
    #pragma unroll
    for (int j = 0; j < 4; j++) c[j] = ((const int4*)counts)[tid * 4 + j];
    int run = 0;
    #pragma unroll
    for (int j = 0; j < 4; j++) run += c[j].x + c[j].y + c[j].z + c[j].w;
    int incl = run;
    #pragma unroll
    for (int m = 1; m < 32; m <<= 1) {
        int t = __shfl_up_sync(0xffffffffu, incl, m);
        if (lane >= m) incl += t;
    }
    if (lane == 31) wsum[w] = incl;
    __syncthreads();
    if (tid == 0) {
        int s = 0;
        #pragma unroll
        for (int i = 0; i < 8; i++) { int t = wsum[i]; wsum[i] = s; s += t; }
    }
    __syncthreads();
    int o = incl - run + wsum[w];
    #pragma unroll
    for (int j = 0; j < 4; j++) {
        int4 out;
        out.x = o; o += c[j].x;
        out.y = o; o += c[j].y;
        out.z = o; o += c[j].z;
        out.w = o; o += c[j].w;
        ((int4*)g_off)[tid * 4 + j] = out;
    }
}

// ---------------- fused kernel: one block = 128x128 tile + 32 negatives ----------------
#define STRIDE     272                   // 256B data + 16B pad; conflict-free ldmatrix
#define TILE_BYTES (128 * STRIDE)        // 34816 per operand
#define SM_TOTAL   (2 * TILE_BYTES)      // 69632

// One 32x32 chunk: 8 k-steps of m16n8k32 fp8
__device__ __forceinline__ void compute_chunk(uint32_t aAddr, uint32_t bAddr,
                                              float acc[2][4][4]) {
    #pragma unroll
    for (int s = 0; s < 8; s++) {
        const uint32_t koff = (uint32_t)s * 32;
        uint32_t a[2][4];
        #pragma unroll
        for (int mi = 0; mi < 2; mi++) {
            asm volatile("ldmatrix.sync.aligned.m8n8.x4.shared.b16 {%0,%1,%2,%3}, [%4];"
                : "=r"(a[mi][0]), "=r"(a[mi][1]), "=r"(a[mi][2]), "=r"(a[mi][3])
                : "r"(aAddr + mi * (16 * STRIDE) + koff));
        }
        uint32_t b[2][4];
        #pragma unroll
        for (int nb = 0; nb < 2; nb++) {
            asm volatile("ldmatrix.sync.aligned.m8n8.x4.shared.b16 {%0,%1,%2,%3}, [%4];"
                : "=r"(b[nb][0]), "=r"(b[nb][1]), "=r"(b[nb][2]), "=r"(b[nb][3])
                : "r"(bAddr + nb * (16 * STRIDE) + koff));
        }
        #pragma unroll
        for (int mi = 0; mi < 2; mi++)
            #pragma unroll
            for (int nb = 0; nb < 2; nb++)
                #pragma unroll
                for (int sub = 0; sub < 2; sub++) {
                    float* d = acc[mi][nb * 2 + sub];
                    asm volatile(
                        "mma.sync.aligned.m16n8k32.row.col.f32.e4m3.e4m3.f32 "
                        "{%0,%1,%2,%3}, {%4,%5,%6,%7}, {%8,%9}, {%0,%1,%2,%3};"
                        : "+f"(d[0]), "+f"(d[1]), "+f"(d[2]), "+f"(d[3])
                        : "r"(a[mi][0]), "r"(a[mi][1]), "r"(a[mi][2]), "r"(a[mi][3]),
                          "r"(b[nb][sub * 2]), "r"(b[nb][sub * 2 + 1]));
                }
    }
}

// Epilogue for one 32x32 chunk: ex2, rsum carry, folded colsum reduce (1 atomic/lane).
__device__ __forceinline__ void epilogue_chunk(float acc[2][4][4], float scale2,
                                               float rsum[4], int lane, int colBase) {
    float e[8];
    #pragma unroll
    for (int v = 0; v < 8; v++) e[v] = 0.f;
    #pragma unroll
    for (int mi = 0; mi < 2; mi++)
        #pragma unroll
        for (int ni = 0; ni < 4; ni++)
            #pragma unroll
            for (int r = 0; r < 4; r++) {
                float ex = ex2(acc[mi][ni][r] * scale2);
                rsum[mi * 2 + (r >> 1)] += ex;
                e[ni * 2 + (r & 1)] += ex;
            }
    // butterfly fold over g-lanes (xor 4,8,16): lane ends with one full column sum
    #pragma unroll
    for (int k = 0; k < 3; k++) {
        int m = 4 << k;
        bool hi = (lane & m) != 0;
        #pragma unroll
        for (int j = 0; j < (4 >> k); j++) {
            float x0 = e[2 * j], x1 = e[2 * j + 1];
            float mine = hi ? x1 : x0;
            float send = hi ? x0 : x1;
            e[j] = mine + __shfl_xor_sync(0xffffffffu, send, m);
        }
    }
    int v = lane >> 2;   // final value index held by this lane
    atomicAdd(&g_colsum[colBase + (v >> 1) * 8 + (lane & 3) * 2 + (v & 1)], e[0]);
}

__global__ __launch_bounds__(256, 3)
void fused_kernel(const float* __restrict__ q, const float* __restrict__ nem,
                  const float* __restrict__ log_tau)
{
    extern __shared__ char smem[];
    const uint32_t sb = smem_u32(smem);
    const int tid  = threadIdx.x;
    const int wid  = tid >> 5;
    const int lane = tid & 31;
    const int bid  = blockIdx.x;            // 0..1023
    const int row0 = (bid >> 5) * 128;
    const int col0 = (bid & 31) * 128;
    const int warpM = (wid >> 1) * 32;
    const int warpN = (wid & 1) * 64;

    // ---- tile loads (fp8, 256B per row, single shot) ----
    {
        const char* qa = (const char*)g_q8 + (size_t)row0 * 256;
        const char* pa = (const char*)g_p8 + (size_t)col0 * 256;
        #pragma unroll
        for (int it = 0; it < 8; it++) {
            int idx = it * 256 + tid;
            int r = idx >> 4, s = idx & 15;
            uint32_t dst = sb + r * STRIDE + s * 16;
            asm volatile("cp.async.cg.shared.global [%0], [%1], 16;"
                         :: "r"(dst), "l"(qa + r * 256 + s * 16));
            asm volatile("cp.async.cg.shared.global [%0], [%1], 16;"
                         :: "r"(dst + TILE_BYTES), "l"(pa + r * 256 + s * 16));
        }
    }
    asm volatile("cp.async.commit_group;" ::: "memory");

    // ---- overlap: binary-search qid for this thread's negative ----
    const int neg = bid * 32 + (tid >> 3);  // 8 threads per negative
    const int l8  = tid & 7;
    int qid;
    {
        int lo = 0, hi = BATCH - 1;
        #pragma unroll
        for (int it = 0; it < 12; it++) {
            int mid = (lo + hi + 1) >> 1;
            if (__ldg(&g_off[mid]) <= neg) lo = mid; else hi = mid - 1;
        }
        qid = lo;
    }
    const float scale  = inv_tau(log_tau);
    const float scale2 = scale * LOG2E;

    asm volatile("cp.async.wait_group 0;" ::: "memory");
    __syncthreads();

    const uint32_t aAddr = sb + (uint32_t)(warpM + (lane & 15)) * STRIDE
                         + (uint32_t)(lane >> 4) * 16;
    const uint32_t bRowSel = (uint32_t)((lane & 7) + ((lane >> 4) << 3)) * STRIDE
                           + (uint32_t)((lane >> 3) & 1) * 16;

    float rsum[4];
    #pragma unroll
    for (int k = 0; k < 4; k++) rsum[k] = 0.f;

    // ---- two 32x32 chunks per warp ----
    #pragma unroll
    for (int chunk = 0; chunk < 2; chunk++) {
        const int nBase = warpN + chunk * 32;
        float acc[2][4][4];
        #pragma unroll
        for (int mi = 0; mi < 2; mi++)
            #pragma unroll
            for (int ni = 0; ni < 4; ni++)
                #pragma unroll
                for (int r = 0; r < 4; r++) acc[mi][ni][r] = 0.f;
        compute_chunk(aAddr, sb + TILE_BYTES + (uint32_t)nBase * STRIDE + bRowSel, acc);
        epilogue_chunk(acc, scale2, rsum, lane, col0 + nBase);
    }

    // ---- row sums: one atomic set per warp ----
    #pragma unroll
    for (int k = 0; k < 4; k++) {
        rsum[k] += __shfl_xor_sync(0xffffffffu, rsum[k], 1);
        rsum[k] += __shfl_xor_sync(0xffffffffu, rsum[k], 2);
    }
    if ((lane & 3) == 0) {
        int g = lane >> 2;
        #pragma unroll
        for (int k = 0; k < 4; k++) {
            int lr = warpM + (k >> 1) * 16 + (k & 1) * 8 + g;
            atomicAdd(&g_rowsum[row0 + lr], rsum[k]);
        }
    }

    // ---- negatives tail: 32 negs, 8 threads each, fp32 exact (L2-hot) ----
    {
        const float4* nr = (const float4*)(nem + (size_t)neg * DIM);
        const float4* qr = (const float4*)(q   + (size_t)qid * DIM);
        float dot = 0.f;
        #pragma unroll
        for (int rd = 0; rd < 2; rd++) {
            float4 nv[4], qv[4];
            #pragma unroll
            for (int j = 0; j < 4; j++) nv[j] = nr[l8 + (rd * 4 + j) * 8];
            #pragma unroll
            for (int j = 0; j < 4; j++) qv[j] = qr[l8 + (rd * 4 + j) * 8];
            #pragma unroll
            for (int j = 0; j < 4; j++)
                dot += qv[j].x * nv[j].x + qv[j].y * nv[j].y
                     + qv[j].z * nv[j].z + qv[j].w * nv[j].w;
        }
        dot += __shfl_xor_sync(0xffffffffu, dot, 1);
        dot += __shfl_xor_sync(0xffffffffu, dot, 2);
        dot += __shfl_xor_sync(0xffffffffu, dot, 4);
        if (l8 == 0)
            atomicAdd(&g_negsum[qid], ex2(dot * scale2));
    }
}

// ---------------- finalize ----------------
__global__ void finalize_kernel(const float* __restrict__ log_tau, float* __restrict__ out) {
    __shared__ float sh[256];
    int tid = threadIdx.x;
    float scale = inv_tau(log_tau);
    float s = 0.f;
    for (int i = tid; i < BATCH; i += 256) {
        float d  = g_diagdot[i] * scale;
        float lq = logf(g_rowsum[i] + g_negsum[i]) - d;
        float lp = logf(g_colsum[i]) - d;
        s += 0.5f * (lq + lp);
    }
    sh[tid] = s;
    __syncthreads();
    #pragma unroll
    for (int off = 128; off >= 32; off >>= 1) {
        if (tid < off) sh[tid] += sh[tid + off];
        __syncthreads();
    }
    if (tid < 32) {
        float v = sh[tid];
        #pragma unroll
        for (int m = 16; m >= 1; m >>= 1)
            v += __shfl_xor_sync(0xffffffffu, v, m);
        if (tid == 0) out[0] = v / (float)BATCH;
    }
}

extern "C" void kernel_launch(void* const* d_in, const int* in_sizes, int n_in,
                              void* d_out, int out_size) {
    const float* q   = (const float*)d_in[0];
    const float* p   = (const float*)d_in[1];
    const float* nem = (const float*)d_in[2];
    const int*   cnt = (const int*)  d_in[3];
    const float* lt  = (const float*)d_in[4];
    float* out = (float*)d_out;

    cudaFuncSetAttribute(fused_kernel,
                         cudaFuncAttributeMaxDynamicSharedMemorySize, SM_TOTAL);

    convert_scan_kernel<<<513, 256>>>(q, p, cnt);
    fused_kernel<<<1024, 256, SM_TOTAL>>>(q, nem, lt);
    finalize_kernel<<<1, 256>>>(lt, out);
}

// round 16
// speedup vs baseline: 2.9264x; 2.9264x over previous
#include <cuda_runtime.h>
#include <cuda_bf16.h>
#include <cuda_fp8.h>
#include <cstdint>

#define BATCH 4096
#define DIM   256
#define NNEG  32768

// ---------------- scratch (device globals; no allocs allowed) ----------------
__device__ float g_rowsum[BATCH];
__device__ float g_colsum[BATCH];
__device__ float g_negsum[BATCH];
__device__ float g_diagdot[BATCH];      // exact fp32 q_i . p_i
__device__ int   g_off[BATCH];          // exclusive prefix of counts
__device__ uint32_t g_q8[BATCH * DIM / 4];   // e4m3x4 packed
__device__ uint32_t g_p8[BATCH * DIM / 4];

__device__ __forceinline__ uint32_t smem_u32(const void* p) {
    uint32_t a;
    asm("{ .reg .u64 t; cvta.to.shared.u64 t, %1; cvt.u32.u64 %0, t; }" : "=r"(a) : "l"(p));
    return a;
}

__device__ __forceinline__ float inv_tau(const float* log_tau) {
    float t = expf(log_tau[0]);
    t = fminf(fmaxf(t, 1e-4f), 1.0f);
    return 1.0f / t;
}

__device__ __forceinline__ float ex2(float x) {
    float r;
    asm("ex2.approx.f32 %0, %1;" : "=f"(r) : "f"(x));
    return r;
}
#define LOG2E 1.4426950408889634f

// ---------------- setup: fp32->fp8 convert + zero + exact diag + scan ----------------
// Blocks 0..127: 1024 threads, 2 float4 each; one warp == one embedding row.
// Block 128: offsets scan + zeroing.
__global__ void convert_scan_kernel(const float* __restrict__ q, const float* __restrict__ p,
                                    const int* __restrict__ counts) {
    int tid = threadIdx.x;
    if (blockIdx.x < 128) {
        int gz = blockIdx.x * 1024 + tid;
        if (gz < BATCH) { g_rowsum[gz] = 0.f; g_colsum[gz] = 0.f; g_negsum[gz] = 0.f; }
        int idx0 = blockIdx.x * 2048 + tid * 2;      // two consecutive float4s
        const float4 qa0 = ((const float4*)q)[idx0];
        const float4 qa1 = ((const float4*)q)[idx0 + 1];
        const float4 pa0 = ((const float4*)p)[idx0];
        const float4 pa1 = ((const float4*)p)[idx0 + 1];
        __nv_fp8x4_e4m3 q80(qa0), q81(qa1), p80(pa0), p81(pa1);
        g_q8[idx0]     = *reinterpret_cast<uint32_t*>(&q80);
        g_q8[idx0 + 1] = *reinterpret_cast<uint32_t*>(&q81);
        g_p8[idx0]     = *reinterpret_cast<uint32_t*>(&p80);
        g_p8[idx0 + 1] = *reinterpret_cast<uint32_t*>(&p81);
        // exact diag: warp w covers exactly row blockIdx.x*32 + w
        float part = qa0.x * pa0.x + qa0.y * pa0.y + qa0.z * pa0.z + qa0.w * pa0.w
                   + qa1.x * pa1.x + qa1.y * pa1.y + qa1.z * pa1.z + qa1.w * pa1.w;
        #pragma unroll
        for (int m = 16; m >= 1; m >>= 1)
            part += __shfl_xor_sync(0xffffffffu, part, m);
        if ((tid & 31) == 0)
            g_diagdot[blockIdx.x * 32 + (tid >> 5)] = part;
        return;
    }
    // ---- scan block: offsets only, fully parallel ----
    __shared__ int wsum[32];
    int lane = tid & 31, w = tid >> 5;
    int4 c4 = ((const int4*)counts)[tid];
    int run = c4.x + c4.y + c4.z + c4.w;
    int incl = run;
    #pragma unroll
    for (int m = 1; m < 32; m <<= 1) {
        int t = __shfl_up_sync(0xffffffffu, incl, m);
        if (lane >= m) incl += t;
    }
    if (lane == 31) wsum[w] = incl;
    __syncthreads();
    if (tid < 32) {
        int v = wsum[tid];
        int s = v;
        #pragma unroll
        for (int m = 1; m < 32; m <<= 1) {
            int t = __shfl_up_sync(0xffffffffu, s, m);
            if (tid >= m) s += t;
        }
        wsum[tid] = s - v;
    }
    __syncthreads();
    int excl = incl - run + wsum[w];
    int4 o;
    o.x = excl;
    o.y = o.x + c4.x;
    o.z = o.y + c4.y;
    o.w = o.z + c4.z;
    ((int4*)g_off)[tid] = o;
}

// ---------------- fused kernel: one block = 128x128 tile + 32 negatives ----------------
// Warp subtile 32x64 processed as two sequential 32x32 chunks (32 accs peak)
// -> <=85 regs -> 3 CTAs/SM (24 warps) for cross-CTA phase overlap.
#define STRIDE     272                   // 256B data + 16B pad; conflict-free ldmatrix
#define TILE_BYTES (128 * STRIDE)        // 34816 per operand
#define SM_TOTAL   (2 * TILE_BYTES)      // 69632

// One 32x32 chunk: 8 k-steps of m16n8k32 fp8 (8 mma per k-step)
__device__ __forceinline__ void compute_chunk(uint32_t aAddr, uint32_t bAddr,
                                              float acc[2][4][4]) {
    #pragma unroll
    for (int s = 0; s < 8; s++) {
        const uint32_t koff = (uint32_t)s * 32;
        uint32_t a[2][4];
        #pragma unroll
        for (int mi = 0; mi < 2; mi++) {
            asm volatile("ldmatrix.sync.aligned.m8n8.x4.shared.b16 {%0,%1,%2,%3}, [%4];"
                : "=r"(a[mi][0]), "=r"(a[mi][1]), "=r"(a[mi][2]), "=r"(a[mi][3])
                : "r"(aAddr + mi * (16 * STRIDE) + koff));
        }
        uint32_t b[2][4];
        #pragma unroll
        for (int nb = 0; nb < 2; nb++) {
            asm volatile("ldmatrix.sync.aligned.m8n8.x4.shared.b16 {%0,%1,%2,%3}, [%4];"
                : "=r"(b[nb][0]), "=r"(b[nb][1]), "=r"(b[nb][2]), "=r"(b[nb][3])
                : "r"(bAddr + nb * (16 * STRIDE) + koff));
        }
        #pragma unroll
        for (int mi = 0; mi < 2; mi++)
            #pragma unroll
            for (int nb = 0; nb < 2; nb++)
                #pragma unroll
                for (int sub = 0; sub < 2; sub++) {
                    float* d = acc[mi][nb * 2 + sub];
                    asm volatile(
                        "mma.sync.aligned.m16n8k32.row.col.f32.e4m3.e4m3.f32 "
                        "{%0,%1,%2,%3}, {%4,%5,%6,%7}, {%8,%9}, {%0,%1,%2,%3};"
                        : "+f"(d[0]), "+f"(d[1]), "+f"(d[2]), "+f"(d[3])
                        : "r"(a[mi][0]), "r"(a[mi][1]), "r"(a[mi][2]), "r"(a[mi][3]),
                          "r"(b[nb][sub * 2]), "r"(b[nb][sub * 2 + 1]));
                }
    }
}

// Epilogue for one 32x32 chunk: ex2, rsum carry, colsum reduce+atomic (R13 structure)
__device__ __forceinline__ void epilogue_chunk(float acc[2][4][4], float scale2,
                                               float rsum[4], int lane, int colBase) {
    float csum[4][2];
    #pragma unroll
    for (int ni = 0; ni < 4; ni++) { csum[ni][0] = 0.f; csum[ni][1] = 0.f; }
    #pragma unroll
    for (int mi = 0; mi < 2; mi++)
        #pragma unroll
        for (int ni = 0; ni < 4; ni++)
            #pragma unroll
            for (int r = 0; r < 4; r++) {
                float e = ex2(acc[mi][ni][r] * scale2);
                rsum[mi * 2 + (r >> 1)] += e;
                csum[ni][r & 1] += e;
            }
    #pragma unroll
    for (int ni = 0; ni < 4; ni++)
        #pragma unroll
        for (int c = 0; c < 2; c++) {
            csum[ni][c] += __shfl_xor_sync(0xffffffffu, csum[ni][c], 4);
            csum[ni][c] += __shfl_xor_sync(0xffffffffu, csum[ni][c], 8);
            csum[ni][c] += __shfl_xor_sync(0xffffffffu, csum[ni][c], 16);
        }
    if (lane < 4) {
        #pragma unroll
        for (int ni = 0; ni < 4; ni++)
            #pragma unroll
            for (int c = 0; c < 2; c++)
                atomicAdd(&g_colsum[colBase + ni * 8 + lane * 2 + c], csum[ni][c]);
    }
}

__global__ __launch_bounds__(256, 3)
void fused_kernel(const float* __restrict__ q, const float* __restrict__ nem,
                  const float* __restrict__ log_tau)
{
    extern __shared__ char smem[];
    const uint32_t sb = smem_u32(smem);
    const int tid  = threadIdx.x;
    const int wid  = tid >> 5;
    const int lane = tid & 31;
    const int bid  = blockIdx.x;            // 0..1023
    const int row0 = (bid >> 5) * 128;
    const int col0 = (bid & 31) * 128;
    const int warpM = (wid >> 1) * 32;
    const int warpN = (wid & 1) * 64;

    // ---- kick off tile loads (fp8, 256B per row, single shot) ----
    {
        const char* qa = (const char*)g_q8 + (size_t)row0 * 256;
        const char* pa = (const char*)g_p8 + (size_t)col0 * 256;
        #pragma unroll
        for (int it = 0; it < 8; it++) {
            int idx = it * 256 + tid;         // 0..2047 16B segments
            int r = idx >> 4, s = idx & 15;
            uint32_t dst = sb + r * STRIDE + s * 16;
            asm volatile("cp.async.cg.shared.global [%0], [%1], 16;"
                         :: "r"(dst), "l"(qa + r * 256 + s * 16));
            asm volatile("cp.async.cg.shared.global [%0], [%1], 16;"
                         :: "r"(dst + TILE_BYTES), "l"(pa + r * 256 + s * 16));
        }
    }
    asm volatile("cp.async.commit_group;" ::: "memory");

    // ---- overlap: binary-search qid for this thread's negative ----
    const int neg = bid * 32 + (tid >> 3);  // 8 threads per negative
    const int l8  = tid & 7;
    int qid;
    {
        int lo = 0, hi = BATCH - 1;
        #pragma unroll
        for (int it = 0; it < 12; it++) {
            int mid = (lo + hi + 1) >> 1;
            if (__ldg(&g_off[mid]) <= neg) lo = mid; else hi = mid - 1;
        }
        qid = lo;
    }
    const float scale2 = inv_tau(log_tau) * LOG2E;

    asm volatile("cp.async.wait_group 0;" ::: "memory");
    __syncthreads();

    const uint32_t aAddr = sb + (uint32_t)(warpM + (lane & 15)) * STRIDE
                         + (uint32_t)(lane >> 4) * 16;
    const uint32_t bRowSel = (uint32_t)((lane & 7) + ((lane >> 4) << 3)) * STRIDE
                           + (uint32_t)((lane >> 3) & 1) * 16;

    float rsum[4];
    #pragma unroll
    for (int k = 0; k < 4; k++) rsum[k] = 0.f;

    // ---- two 32x32 chunks per warp (halved accumulator footprint) ----
    #pragma unroll
    for (int chunk = 0; chunk < 2; chunk++) {
        const int nBase = warpN + chunk * 32;
        float acc[2][4][4];
        #pragma unroll
        for (int mi = 0; mi < 2; mi++)
            #pragma unroll
            for (int ni = 0; ni < 4; ni++)
                #pragma unroll
                for (int r = 0; r < 4; r++) acc[mi][ni][r] = 0.f;
        compute_chunk(aAddr, sb + TILE_BYTES + (uint32_t)nBase * STRIDE + bRowSel, acc);
        epilogue_chunk(acc, scale2, rsum, lane, col0 + nBase);
    }

    // ---- row sums: one atomic set per warp ----
    #pragma unroll
    for (int k = 0; k < 4; k++) {
        rsum[k] += __shfl_xor_sync(0xffffffffu, rsum[k], 1);
        rsum[k] += __shfl_xor_sync(0xffffffffu, rsum[k], 2);
    }
    if ((lane & 3) == 0) {
        int g = lane >> 2;
        #pragma unroll
        for (int k = 0; k < 4; k++) {
            int lr = warpM + (k >> 1) * 16 + (k & 1) * 8 + g;
            atomicAdd(&g_rowsum[row0 + lr], rsum[k]);
        }
    }

    // ---- negatives: 32 negs, 8 threads each, two 4xfloat4 rounds (low reg burst) ----
    {
        const float4* nr = (const float4*)(nem + (size_t)neg * DIM);
        const float4* qr = (const float4*)(q   + (size_t)qid * DIM);
        float dot = 0.f;
        #pragma unroll
        for (int rd = 0; rd < 2; rd++) {
            float4 nv[4], qv[4];
            #pragma unroll
            for (int j = 0; j < 4; j++) nv[j] = nr[l8 + (rd * 4 + j) * 8];
            #pragma unroll
            for (int j = 0; j < 4; j++) qv[j] = qr[l8 + (rd * 4 + j) * 8];
            #pragma unroll
            for (int j = 0; j < 4; j++)
                dot += qv[j].x * nv[j].x + qv[j].y * nv[j].y
                     + qv[j].z * nv[j].z + qv[j].w * nv[j].w;
        }
        dot += __shfl_xor_sync(0xffffffffu, dot, 1);
        dot += __shfl_xor_sync(0xffffffffu, dot, 2);
        dot += __shfl_xor_sync(0xffffffffu, dot, 4);
        if (l8 == 0)
            atomicAdd(&g_negsum[qid], ex2(dot * scale2));
    }
}

// ---------------- finalize ----------------
__global__ void finalize_kernel(const float* __restrict__ log_tau, float* __restrict__ out) {
    __shared__ float sh[256];
    int tid = threadIdx.x;
    float scale = inv_tau(log_tau);
    float s = 0.f;
    for (int i = tid; i < BATCH; i += 256) {
        float d  = g_diagdot[i] * scale;
        float lq = logf(g_rowsum[i] + g_negsum[i]) - d;
        float lp = logf(g_colsum[i]) - d;
        s += 0.5f * (lq + lp);
    }
    sh[tid] = s;
    __syncthreads();
    #pragma unroll
    for (int off = 128; off >= 32; off >>= 1) {
        if (tid < off) sh[tid] += sh[tid + off];
        __syncthreads();
    }
    if (tid < 32) {
        float v = sh[tid];
        #pragma unroll
        for (int m = 16; m >= 1; m >>= 1)
            v += __shfl_xor_sync(0xffffffffu, v, m);
        if (tid == 0) out[0] = v / (float)BATCH;
    }
}

extern "C" void kernel_launch(void* const* d_in, const int* in_sizes, int n_in,
                              void* d_out, int out_size) {
    const float* q   = (const float*)d_in[0];
    const float* p   = (const float*)d_in[1];
    const float* nem = (const float*)d_in[2];
    const int*   cnt = (const int*)  d_in[3];
    const float* lt  = (const float*)d_in[4];
    float* out = (float*)d_out;

    cudaFuncSetAttribute(fused_kernel,
                         cudaFuncAttributeMaxDynamicSharedMemorySize, SM_TOTAL);

    convert_scan_kernel<<<129, 1024>>>(q, p, cnt);
    fused_kernel<<<1024, 256, SM_TOTAL>>>(q, nem, lt);
    finalize_kernel<<<1, 256>>>(lt, out);
}